// round 4
// baseline (speedup 1.0000x reference)
#include <cuda_runtime.h>

#define BATCH   16
#define CHN     512
#define HW      4096            // 64*64
#define NCLS    5
#define NSEG    (BATCH * NCLS)  // 80
#define NPIX    (BATCH * HW)    // 65536
#define CCHUNKS 8
#define CPER    (CHN / CCHUNKS) // 64
#define JBLKS   4
#define NBLOCKS (BATCH * CCHUNKS * JBLKS) // 512
#define BETA    2.0f
#define EPS2    (0.001f * 0.001f)

// per-block partial segment sums (sum of squared diffs, not yet /CHN)
__device__ float g_bsum[NBLOCKS * NCLS];
// per-(b,jblk)-block mask histogram counts (only k==0 blocks write)
__device__ float g_bcnt[BATCH * JBLKS * NCLS];

// ---------------------------------------------------------------- kernel 1
// grid = 512 blocks × 256 threads. Block (b, k, jblk): thread owns one float4
// (4 pixels) and a 64-channel slice; accumulates squared diffs in registers,
// bins the 4 partial sums by mask class into a 5-bin shared histogram,
// writes block bins to global (no global atomics, no zeroing needed).
__global__ void frl_mse(const float4* __restrict__ rec,
                        const float4* __restrict__ ali,
                        const int4*  __restrict__ mask) {
    __shared__ float ssum[NCLS];
    __shared__ float scnt[NCLS];
    const int bid  = blockIdx.x;
    const int jblk = bid & 3;          // 4 j-blocks of 256 float4s
    const int k    = (bid >> 2) & 7;   // channel chunk
    const int b    = bid >> 5;         // batch
    const int tid  = threadIdx.x;

    if (tid < NCLS) { ssum[tid] = 0.0f; scnt[tid] = 0.0f; }
    __syncthreads();

    const int j = jblk * 256 + tid;    // float4 index within image, 0..1023
    const int S = HW / 4;              // 1024 float4 per channel plane

    int base = (b * CHN + k * CPER) * S + j;

    float ax = 0.f, ay = 0.f, az = 0.f, aw = 0.f;
    #pragma unroll 8
    for (int c = 0; c < CPER; ++c) {
        float4 r = rec[base + c * S];
        float4 a = ali[base + c * S];
        float dx = r.x - a.x, dy = r.y - a.y, dz = r.z - a.z, dw = r.w - a.w;
        ax += dx * dx; ay += dy * dy; az += dz * dz; aw += dw * dw;
    }

    const int4 m = mask[b * S + j];
    atomicAdd(&ssum[m.x], ax);
    atomicAdd(&ssum[m.y], ay);
    atomicAdd(&ssum[m.z], az);
    atomicAdd(&ssum[m.w], aw);
    if (k == 0) {
        atomicAdd(&scnt[m.x], 1.0f);
        atomicAdd(&scnt[m.y], 1.0f);
        atomicAdd(&scnt[m.z], 1.0f);
        atomicAdd(&scnt[m.w], 1.0f);
    }
    __syncthreads();

    if (tid < NCLS) {
        g_bsum[bid * NCLS + tid] = ssum[tid];
        if (k == 0)
            g_bcnt[(b * JBLKS + jblk) * NCLS + tid] = scnt[tid];
    }
}

// ---------------------------------------------------------------- kernel 2
// Single block: reduce block bins -> segment sums/counts -> segment means ->
// wmax -> per-segment weight coefficients -> final loss, written directly.
//   loss = (1/NPIX) * sum_seg segsum_seg * (clip(w_seg)*BETA + 1)
__global__ void frl_fin(float* __restrict__ out) {
    __shared__ float s_sum[NSEG];   // sum of lm over segment pixels
    __shared__ float s_avg[NSEG];   // segment mean of lm
    __shared__ float red[128];
    const int t = threadIdx.x;

    if (t < NSEG) {
        const int b = t / NCLS, cls = t % NCLS;
        float ss = 0.0f, cnt = 0.0f;
        #pragma unroll
        for (int i = 0; i < CCHUNKS * JBLKS; ++i)
            ss += g_bsum[(b * (CCHUNKS * JBLKS) + i) * NCLS + cls];
        #pragma unroll
        for (int jb = 0; jb < JBLKS; ++jb)
            cnt += g_bcnt[(b * JBLKS + jb) * NCLS + cls];
        const float lmsum = ss * (1.0f / CHN);
        s_sum[t] = lmsum;
        s_avg[t] = lmsum / fmaxf(cnt, 1.0f);
    }

    // max over segment means (empty segments give 0; lm>=0 so max unaffected)
    red[t] = (t < NSEG) ? s_avg[t] : 0.0f;
    __syncthreads();
    #pragma unroll
    for (int s = 64; s > 0; s >>= 1) {
        if (t < s) red[t] = fmaxf(red[t], red[t + s]);
        __syncthreads();
    }
    const float wmax = red[0];
    __syncthreads();

    float part = 0.0f;
    if (t < NSEG) {
        float a = s_avg[t];
        float w = (wmax > 0.0f) ? a / (wmax + EPS2) : a + EPS2;
        w = fminf(fmaxf(w, 0.0f), 1.0f);
        part = s_sum[t] * (w * BETA + 1.0f);
    }
    red[t] = part;
    __syncthreads();
    #pragma unroll
    for (int s = 64; s > 0; s >>= 1) {
        if (t < s) red[t] += red[t + s];
        __syncthreads();
    }
    if (t == 0) out[0] = red[0] * (1.0f / NPIX);
}

// ---------------------------------------------------------------- launch
extern "C" void kernel_launch(void* const* d_in, const int* in_sizes, int n_in,
                              void* d_out, int out_size) {
    const float4* rec  = (const float4*)d_in[0];
    const float4* ali  = (const float4*)d_in[1];
    const int4*   mask = (const int4*)d_in[2];
    float*        out  = (float*)d_out;

    frl_mse<<<NBLOCKS, 256>>>(rec, ali, mask);
    frl_fin<<<1, 128>>>(out);
}